// round 3
// baseline (speedup 1.0000x reference)
#include <cuda_runtime.h>
#include <cstdint>

// HexPool: out[i, :] = max_{k<7} x[neigh_indices[i,k], :]
// x: (655362, 64) f32 ; neigh_indices: (163842, 7) int32 (JAX downcasts i64->i32
// without x64 mode) ; out: (163842, 64) f32
// One thread per float4 of output -> 16 threads per output row (one half-warp).
// Gathered rows are 256B contiguous => fully coalesced 16x float4 loads.
// No divergent exits: tail threads clamp their row and skip only the store,
// so every __shfl_sync sees a fully converged warp.

#define N_OUT 163842
#define KNB   7
#define VEC_PER_ROW 16   // 64 floats / 4

__global__ __launch_bounds__(256) void hexpool_kernel(
    const float4* __restrict__ x,          // viewed as [n_in][16] float4
    const int* __restrict__ idx,           // [N_OUT][7] int32
    float4* __restrict__ out)               // [N_OUT][16] float4
{
    const int gid = blockIdx.x * blockDim.x + threadIdx.x;
    const int row_raw = gid >> 4;                 // output row (may overshoot in tail)
    const int row = row_raw < N_OUT ? row_raw : (N_OUT - 1);
    const int col = gid & 15;                     // float4 column within row

    const int lane = threadIdx.x & 31;
    const int half_base = lane & 16;              // 0 or 16: start lane of my half-warp
    const int sub = lane & 15;

    // Lanes sub<7 of each half-warp load the 7 indices for this half-warp's row.
    int my_idx = 0;
    if (sub < KNB) {
        my_idx = __ldg(&idx[row * KNB + sub]);
    }

    float4 m = make_float4(-3.402823466e+38f, -3.402823466e+38f,
                           -3.402823466e+38f, -3.402823466e+38f);

    #pragma unroll
    for (int k = 0; k < KNB; ++k) {
        int j = __shfl_sync(0xFFFFFFFFu, my_idx, half_base + k);
        float4 v = __ldg(&x[(long long)j * VEC_PER_ROW + col]);
        m.x = fmaxf(m.x, v.x);
        m.y = fmaxf(m.y, v.y);
        m.z = fmaxf(m.z, v.z);
        m.w = fmaxf(m.w, v.w);
    }

    if (row_raw < N_OUT) {
        out[gid] = m;
    }
}

extern "C" void kernel_launch(void* const* d_in, const int* in_sizes, int n_in,
                              void* d_out, int out_size)
{
    const float4* x   = (const float4*)d_in[0];
    const int*    idx = (const int*)d_in[1];
    float4*       out = (float4*)d_out;

    const int total_threads = N_OUT * VEC_PER_ROW;   // 2,621,472
    const int block = 256;
    const int grid  = (total_threads + block - 1) / block;
    hexpool_kernel<<<grid, block>>>(x, idx, out);
}